// round 5
// baseline (speedup 1.0000x reference)
#include <cuda_runtime.h>
#include <cuda_bf16.h>
#include <cstdint>

// ===========================================================================
// PackedSirenExperts via mma.sync m16n8k16 bf16 (portable PTX, compute_103).
// R5: barrier-free mainloop. B fragments streamed directly from L2 via
// LDG.128 (prep kernel packs {Whi,Wlo} per fragment as one uint4), 3-deep
// register pipeline. A fragments via ldmatrix.x4 from swizzled SMEM.
// Only sync: 2 named pair-barriers (wm row-pair, 64 threads) per layer.
// 3-term bf16 split: D += Ahi*Whi + Alo*Whi + Ahi*Wlo (fp32 accum).
// CTA = (expert, 64 rows), 128 threads = 2(wm) x 2(wn), warp tile 32x128.
// ===========================================================================

namespace {
constexpr int Mexp = 64;
constexpr int Bdim = 8192;
constexpr float W0F = 30.0f;

constexpr int OFF_AHI  = 0;          // 64 rows x 512B swizzled bf16 (32K)
constexpr int OFF_ALO  = 32768;      // 32K
constexpr int OFF_W0   = 65536;      // 768 f
constexpr int OFF_WF   = 68608;      // 768 f
constexpr int OFF_B0   = 71680;      // 256 f
constexpr int OFF_B123 = 72704;      // 768 f
constexpr int OFF_X    = 75776;      // 192 f
constexpr int OFF_PBUF = 76544;      // 384 f
constexpr int SMEM_TOTAL = 78080;
}

// prepped weights: slab blob = [m][layer*16 + s] of 16KB:
// 256 o-rows x 64B; row = 4 q x uint4 {hi(k=2q,2q+1), hi(k=2q+8,2q+9),
//                                      lo(k=2q,2q+1), lo(k=2q+8,2q+9)}
__device__ __align__(16) unsigned char g_wp[(size_t)Mexp * 48 * 16384];

// ---------------------------------------------------------------------------
__device__ __forceinline__ uint32_t smem_u32(const void* p) {
    uint32_t a;
    asm("{ .reg .u64 t; cvta.to.shared.u64 t, %1; cvt.u32.u64 %0, t; }" : "=r"(a) : "l"(p));
    return a;
}
__device__ __forceinline__ uint32_t pack2(float v0, float v1) {
    __nv_bfloat162 t = __floats2bfloat162_rn(v0, v1);
    return *reinterpret_cast<uint32_t*>(&t);
}
__device__ __forceinline__ uint32_t pack2lo(float v0, float v1) {
    __nv_bfloat16 h0 = __float2bfloat16(v0);
    __nv_bfloat16 h1 = __float2bfloat16(v1);
    __nv_bfloat162 t = __floats2bfloat162_rn(v0 - __bfloat162float(h0),
                                             v1 - __bfloat162float(h1));
    return *reinterpret_cast<uint32_t*>(&t);
}
// A swizzled byte offset: row r (0..63), col k (0..255) bf16
__device__ __forceinline__ uint32_t aoff(int r, int k) {
    return (uint32_t)(r * 512 + ((((k >> 3) ^ (r & 7)) << 4) | ((k & 7) * 2)));
}
__device__ __forceinline__ void mma16816(float* d, const uint32_t* a,
                                         uint32_t b0, uint32_t b1) {
    asm volatile(
        "mma.sync.aligned.m16n8k16.row.col.f32.bf16.bf16.f32 "
        "{%0,%1,%2,%3}, {%4,%5,%6,%7}, {%8,%9}, {%0,%1,%2,%3};"
        : "+f"(d[0]), "+f"(d[1]), "+f"(d[2]), "+f"(d[3])
        : "r"(a[0]), "r"(a[1]), "r"(a[2]), "r"(a[3]), "r"(b0), "r"(b1));
}
__device__ __forceinline__ void ldsm4(uint32_t* r, uint32_t addr) {
    asm volatile("ldmatrix.sync.aligned.m8n8.x4.shared.b16 {%0,%1,%2,%3}, [%4];"
                 : "=r"(r[0]), "=r"(r[1]), "=r"(r[2]), "=r"(r[3]) : "r"(addr));
}
__device__ __forceinline__ void barpair(int id) {
    asm volatile("bar.sync %0, 64;" :: "r"(id) : "memory");
}

// ---------------------------------------------------------------------------
// Prep: fp32 W[m][o][i] -> fragment uint4 blobs (hi|lo fused per fragment).
// One thread per (m, slab, o).
// ---------------------------------------------------------------------------
__global__ void prep_weights(const float* __restrict__ w, int layer) {
    int id = blockIdx.x * blockDim.x + threadIdx.x;   // 262144
    int o = id & 255;
    int s = (id >> 8) & 15;
    int m = id >> 12;
    const float* src = w + ((size_t)m * 256 + o) * 256 + s * 16;
    unsigned char* dst = g_wp + (size_t)(m * 48 + layer * 16 + s) * 16384 + o * 64;
#pragma unroll
    for (int q = 0; q < 4; q++) {
        float f0 = src[2 * q],     f1 = src[2 * q + 1];
        float f2 = src[2 * q + 8], f3 = src[2 * q + 9];
        uint4 v;
        v.x = pack2(f0, f1);   v.y = pack2(f2, f3);
        v.z = pack2lo(f0, f1); v.w = pack2lo(f2, f3);
        *reinterpret_cast<uint4*>(dst + q * 16) = v;
    }
}

// ---------------------------------------------------------------------------
// Main kernel. grid = Mexp*128 = 8192 CTAs (expert-major), 128 threads.
// ---------------------------------------------------------------------------
__global__ void __launch_bounds__(128, 2)
siren_mma(const float* __restrict__ x,
          const float* __restrict__ w0, const float* __restrict__ b0,
          const float* __restrict__ b1, const float* __restrict__ b2,
          const float* __restrict__ b3,
          const float* __restrict__ wf, const float* __restrict__ bf,
          float* __restrict__ out) {
    extern __shared__ __align__(16) unsigned char smem[];
    const uint32_t sb = smem_u32(smem);
    float* w0s  = reinterpret_cast<float*>(smem + OFF_W0);
    float* wfs  = reinterpret_cast<float*>(smem + OFF_WF);
    float* b0s  = reinterpret_cast<float*>(smem + OFF_B0);
    float* b123 = reinterpret_cast<float*>(smem + OFF_B123);
    float* xs   = reinterpret_cast<float*>(smem + OFF_X);
    float* pbuf = reinterpret_cast<float*>(smem + OFF_PBUF);

    const int tid  = threadIdx.x;
    const int lane = tid & 31;
    const int wid  = tid >> 5;
    const int wm   = wid & 1;          // m-tile: rows wm*32..+31
    const int wn   = wid >> 1;         // n-half: cols wn*128..+127
    const int rl   = lane >> 2;        // 0..7
    const int q    = lane & 3;         // 0..3
    const int m    = blockIdx.x >> 7;
    const int bt   = blockIdx.x & 127;
    const int row0 = bt * 64;
    const int barid = 1 + wm;

    // ldmatrix lane addressing: row = base + (lane&15), col-half = lane>>4
    const int lrow  = lane & 15;
    const int lhalf = lane >> 4;

    // ---- stage small tensors ----
    for (int i = tid; i < 768; i += 128) w0s[i] = w0[m * 768 + i];
    for (int i = tid; i < 768; i += 128) wfs[i] = wf[m * 768 + i];
    for (int i = tid; i < 256; i += 128) {
        b0s[i]        = b0[m * 256 + i];
        b123[i]       = b1[m * 256 + i];
        b123[256 + i] = b2[m * 256 + i];
        b123[512 + i] = b3[m * 256 + i];
    }
    for (int i = tid; i < 192; i += 128) xs[i] = x[(size_t)row0 * 3 + i];
    __syncthreads();

    // ---- layer 0: per-warp region rows [wm*32,+32) x cols [wn*128,+128) ----
    {
        const int rbase = wm * 32, cbase = wn * 128;
#pragma unroll 4
        for (int i = 0; i < 64; i++) {
            int pid = lane + i * 32;
            int r = rbase + (pid >> 6);
            int c = cbase + (pid & 63) * 2;
            float x0 = xs[r * 3], x1 = xs[r * 3 + 1], x2 = xs[r * 3 + 2];
            float p0 = fmaf(x2, w0s[c * 3 + 2], fmaf(x1, w0s[c * 3 + 1],
                       fmaf(x0, w0s[c * 3 + 0], b0s[c])));
            float p1 = fmaf(x2, w0s[c * 3 + 5], fmaf(x1, w0s[c * 3 + 4],
                       fmaf(x0, w0s[c * 3 + 3], b0s[c + 1])));
            float v0 = __sinf(W0F * p0);
            float v1 = __sinf(W0F * p1);
            uint32_t ao = aoff(r, c);
            *reinterpret_cast<uint32_t*>(smem + OFF_AHI + ao) = pack2(v0, v1);
            *reinterpret_cast<uint32_t*>(smem + OFF_ALO + ao) = pack2lo(v0, v1);
        }
    }
    barpair(barid);   // pair writes visible before layer-1 MMA reads

    // per-thread B fragment base (uint4 units within a 16KB slab = 1024 uint4)
    const int bidx = (wn * 128 + rl) * 4 + q;

    // ---- 3 hidden layers ----
#pragma unroll 1
    for (int L = 0; L < 3; L++) {
        const uint4* wbL = reinterpret_cast<const uint4*>(
            g_wp + (size_t)(m * 48 + L * 16) * 16384);

        float acc[16][2][4];
#pragma unroll
        for (int n = 0; n < 16; n++)
#pragma unroll
            for (int f = 0; f < 2; f++)
#pragma unroll
                for (int v = 0; v < 4; v++) acc[n][f][v] = 0.0f;

        // 3-deep B pipeline
        uint4 c0 = __ldg(wbL + 0 * 32 + bidx);
        uint4 c1 = __ldg(wbL + 1 * 32 + bidx);
        uint4 c2 = __ldg(wbL + 2 * 32 + bidx);

        uint32_t ah[2][4], al[2][4];

#pragma unroll 1
        for (int s = 0; s < 16; s++) {
            // A fragments for this k16 slab (ldmatrix.x4, hi & lo, f=0,1)
            {
                int c3 = (s * 2 + lhalf);
#pragma unroll
                for (int f = 0; f < 2; f++) {
                    int row = wm * 32 + f * 16 + lrow;
                    uint32_t ad = sb + (uint32_t)(row * 512 + (((c3) ^ (row & 7)) << 4));
                    ldsm4(ah[f], ad);
                    ldsm4(al[f], ad + 32768);
                }
            }
#pragma unroll
            for (int n = 0; n < 16; n++) {
                int t = s * 16 + n;
                int u = t + 3; if (u > 255) u = 255;
                uint4 nn = __ldg(wbL + (u >> 4) * 1024 + (u & 15) * 32 + bidx);
#pragma unroll
                for (int f = 0; f < 2; f++) {
                    mma16816(acc[n][f], ah[f], c0.x, c0.y);
                    mma16816(acc[n][f], al[f], c0.x, c0.y);
                    mma16816(acc[n][f], ah[f], c0.z, c0.w);
                }
                c0 = c1; c1 = c2; c2 = nn;
            }
        }

        barpair(barid);   // pair done READING A rows before we overwrite them

        if (L < 2) {
            const float* bl = b123 + L * 256;
#pragma unroll
            for (int n = 0; n < 16; n++) {
#pragma unroll
                for (int f = 0; f < 2; f++) {
                    int r   = wm * 32 + f * 16 + rl;
                    int col = wn * 128 + n * 8 + q * 2;
                    float bb0 = bl[col], bb1 = bl[col + 1];
                    float v0 = __sinf(W0F * (acc[n][f][0] + bb0));
                    float v1 = __sinf(W0F * (acc[n][f][1] + bb1));
                    float v2 = __sinf(W0F * (acc[n][f][2] + bb0));
                    float v3 = __sinf(W0F * (acc[n][f][3] + bb1));
                    uint32_t a0 = aoff(r, col);
                    uint32_t a1 = aoff(r + 8, col);
                    *reinterpret_cast<uint32_t*>(smem + OFF_AHI + a0) = pack2(v0, v1);
                    *reinterpret_cast<uint32_t*>(smem + OFF_ALO + a0) = pack2lo(v0, v1);
                    *reinterpret_cast<uint32_t*>(smem + OFF_AHI + a1) = pack2(v2, v3);
                    *reinterpret_cast<uint32_t*>(smem + OFF_ALO + a1) = pack2lo(v2, v3);
                }
            }
            barpair(barid);   // pair writes visible before next-layer MMA reads
        } else {
            // final: sine + wf dot (3 outputs), partial per n-half
            const float* bl = b123 + 512;
            float p[4][3];
#pragma unroll
            for (int i = 0; i < 4; i++)
#pragma unroll
                for (int o = 0; o < 3; o++) p[i][o] = 0.0f;
#pragma unroll
            for (int n = 0; n < 16; n++) {
#pragma unroll
                for (int f = 0; f < 2; f++) {
                    int col = wn * 128 + n * 8 + q * 2;
                    float bb0 = bl[col], bb1 = bl[col + 1];
                    float v0 = __sinf(W0F * (acc[n][f][0] + bb0));
                    float v1 = __sinf(W0F * (acc[n][f][1] + bb1));
                    float v2 = __sinf(W0F * (acc[n][f][2] + bb0));
                    float v3 = __sinf(W0F * (acc[n][f][3] + bb1));
#pragma unroll
                    for (int o = 0; o < 3; o++) {
                        float wf0 = wfs[o * 256 + col], wf1 = wfs[o * 256 + col + 1];
                        p[f * 2 + 0][o] = fmaf(v0, wf0, fmaf(v1, wf1, p[f * 2 + 0][o]));
                        p[f * 2 + 1][o] = fmaf(v2, wf0, fmaf(v3, wf1, p[f * 2 + 1][o]));
                    }
                }
            }
#pragma unroll
            for (int i = 0; i < 4; i++)
#pragma unroll
                for (int o = 0; o < 3; o++) {
                    p[i][o] += __shfl_xor_sync(0xffffffffu, p[i][o], 1);
                    p[i][o] += __shfl_xor_sync(0xffffffffu, p[i][o], 2);
                }
            // pbuf[wm][wn][32 rows x 3]
            if (q == 0) {
#pragma unroll
                for (int f = 0; f < 2; f++)
#pragma unroll
                    for (int pr = 0; pr < 2; pr++) {
                        int rloc = f * 16 + pr * 8 + rl;   // 0..31 within wm tile
#pragma unroll
                        for (int o = 0; o < 3; o++)
                            pbuf[wm * 192 + wn * 96 + rloc * 3 + o] = p[f * 2 + pr][o];
                    }
            }
            barpair(barid);
            // combine halves: pair-local tid covers 96 entries of this wm tile
            int ptid = wn * 32 + lane;   // 0..63
            for (int i = ptid; i < 96; i += 64) {
                int rloc = i / 3, o = i - rloc * 3;
                float v = pbuf[wm * 192 + i] + pbuf[wm * 192 + 96 + i] + bf[m * 3 + o];
                out[((size_t)(row0 + wm * 32 + rloc) * Mexp + m) * 3 + o] = v;
            }
        }
    }
}

// ---------------------------------------------------------------------------
extern "C" void kernel_launch(void* const* d_in, const int* in_sizes, int n_in,
                              void* d_out, int out_size) {
    (void)in_sizes; (void)n_in; (void)out_size;
    const float* x  = (const float*)d_in[0];
    const float* w0 = (const float*)d_in[1];
    const float* b0 = (const float*)d_in[2];
    const float* w1 = (const float*)d_in[3];
    const float* b1 = (const float*)d_in[4];
    const float* w2 = (const float*)d_in[5];
    const float* b2 = (const float*)d_in[6];
    const float* w3 = (const float*)d_in[7];
    const float* b3 = (const float*)d_in[8];
    const float* wf = (const float*)d_in[9];
    const float* bf = (const float*)d_in[10];
    float* out = (float*)d_out;

    cudaFuncSetAttribute(siren_mma, cudaFuncAttributeMaxDynamicSharedMemorySize,
                         SMEM_TOTAL);

    prep_weights<<<1024, 256>>>(w1, 0);
    prep_weights<<<1024, 256>>>(w2, 1);
    prep_weights<<<1024, 256>>>(w3, 2);

    siren_mma<<<Mexp * (Bdim / 64), 128, SMEM_TOTAL>>>(
        x, w0, b0, b1, b2, b3, wf, bf, out);
}

// round 6
// speedup vs baseline: 1.1974x; 1.1974x over previous
#include <cuda_runtime.h>
#include <cuda_bf16.h>
#include <cstdint>

// ===========================================================================
// PackedSirenExperts via mma.sync m16n8k16 bf16 (portable PTX, compute_103).
// R6: R4 cp.async-staged structure, but ALL full-CTA barriers replaced by
// dependency-scoped 64-thread named barriers:
//   A-tile hazards  -> wm-pair barrier (ids 1,2), 2 per layer
//   B-buffer hazards-> wn-pair barrier (ids 3,4), 1 per slab; each wn pair
//                      stages only its own o-half of each weight slab.
// A fragments via ldmatrix.x4. 3-term bf16 split (fp32 accum):
//   D += Ahi*Whi + Alo*Whi + Ahi*Wlo
// CTA = (expert, 64 rows), 128 thr = 2(wm) x 2(wn), warp tile 32x128.
// 2 CTAs/SM (110.8 KB smem).
// ===========================================================================

namespace {
constexpr int Mexp = 64;
constexpr int Bdim = 8192;
constexpr float W0F = 30.0f;

constexpr int OFF_AHI  = 0;          // 64 rows x 512B swizzled bf16 (32K)
constexpr int OFF_ALO  = 32768;      // 32K
constexpr int OFF_WBUF = 65536;      // 2 x 16384 (double-buffered k16 slab)
constexpr int OFF_W0   = 98304;      // 768 f
constexpr int OFF_WF   = 101376;     // 768 f
constexpr int OFF_B0   = 104448;     // 256 f
constexpr int OFF_B123 = 105472;     // 768 f
constexpr int OFF_X    = 108544;     // 192 f
constexpr int OFF_PBUF = 109312;     // 384 f (NOT aliased)
constexpr int SMEM_TOTAL = 110848;
}

// prepped weights: slab blob = [m][layer*16 + s] of 16KB:
//   [hi: 256 o-rows x 32B][lo: 256 x 32B]; row = 4 q-words (uint2):
//   {bf16x2(k=2q,2q+1), bf16x2(k=2q+8,2q+9)} within the 16-wide k slab.
__device__ __align__(16) unsigned char g_wp[(size_t)Mexp * 48 * 16384];

// ---------------------------------------------------------------------------
__device__ __forceinline__ uint32_t smem_u32(const void* p) {
    uint32_t a;
    asm("{ .reg .u64 t; cvta.to.shared.u64 t, %1; cvt.u32.u64 %0, t; }" : "=r"(a) : "l"(p));
    return a;
}
__device__ __forceinline__ void cp16(uint32_t s, const void* g) {
    asm volatile("cp.async.cg.shared.global [%0], [%1], 16;" :: "r"(s), "l"(g));
}
__device__ __forceinline__ void cp_commit() { asm volatile("cp.async.commit_group;"); }
__device__ __forceinline__ void cp_wait0() {
    asm volatile("cp.async.wait_group 0;" ::: "memory");
}
__device__ __forceinline__ uint32_t pack2(float v0, float v1) {
    __nv_bfloat162 t = __floats2bfloat162_rn(v0, v1);
    return *reinterpret_cast<uint32_t*>(&t);
}
__device__ __forceinline__ uint32_t pack2lo(float v0, float v1) {
    __nv_bfloat16 h0 = __float2bfloat16(v0);
    __nv_bfloat16 h1 = __float2bfloat16(v1);
    __nv_bfloat162 t = __floats2bfloat162_rn(v0 - __bfloat162float(h0),
                                             v1 - __bfloat162float(h1));
    return *reinterpret_cast<uint32_t*>(&t);
}
// A swizzled byte offset: row r (0..63), col k (0..255) bf16
__device__ __forceinline__ uint32_t aoff(int r, int k) {
    return (uint32_t)(r * 512 + ((((k >> 3) ^ (r & 7)) << 4) | ((k & 7) * 2)));
}
__device__ __forceinline__ void mma16816(float* d, const uint32_t* a,
                                         uint32_t b0, uint32_t b1) {
    asm volatile(
        "mma.sync.aligned.m16n8k16.row.col.f32.bf16.bf16.f32 "
        "{%0,%1,%2,%3}, {%4,%5,%6,%7}, {%8,%9}, {%0,%1,%2,%3};"
        : "+f"(d[0]), "+f"(d[1]), "+f"(d[2]), "+f"(d[3])
        : "r"(a[0]), "r"(a[1]), "r"(a[2]), "r"(a[3]), "r"(b0), "r"(b1));
}
__device__ __forceinline__ void ldsm4(uint32_t* r, uint32_t addr) {
    asm volatile("ldmatrix.sync.aligned.m8n8.x4.shared.b16 {%0,%1,%2,%3}, [%4];"
                 : "=r"(r[0]), "=r"(r[1]), "=r"(r[2]), "=r"(r[3]) : "r"(addr));
}
__device__ __forceinline__ void barn(int id) {
    asm volatile("bar.sync %0, 64;" :: "r"(id) : "memory");
}

// ---------------------------------------------------------------------------
// Prep: fp32 W[m][o][i] -> k16-slab blobs (hi 8K | lo 8K per 16KB slab).
// ---------------------------------------------------------------------------
__global__ void prep_weights(const float* __restrict__ w, int layer) {
    int id = blockIdx.x * blockDim.x + threadIdx.x;   // 262144
    int o = id & 255;
    int s = (id >> 8) & 15;
    int m = id >> 12;
    const float* src = w + ((size_t)m * 256 + o) * 256 + s * 16;
    unsigned char* dst = g_wp + (size_t)(m * 48 + layer * 16 + s) * 16384 + o * 32;
#pragma unroll
    for (int q = 0; q < 4; q++) {
        float f0 = src[2 * q],     f1 = src[2 * q + 1];
        float f2 = src[2 * q + 8], f3 = src[2 * q + 9];
        uint2 hv, lv;
        hv.x = pack2(f0, f1);   hv.y = pack2(f2, f3);
        lv.x = pack2lo(f0, f1); lv.y = pack2lo(f2, f3);
        *reinterpret_cast<uint2*>(dst + q * 8) = hv;
        *reinterpret_cast<uint2*>(dst + 8192 + q * 8) = lv;
    }
}

// ---------------------------------------------------------------------------
// Main kernel. grid = Mexp*128 = 8192 CTAs (expert-major), 128 threads.
// ---------------------------------------------------------------------------
__global__ void __launch_bounds__(128, 2)
siren_mma(const float* __restrict__ x,
          const float* __restrict__ w0, const float* __restrict__ b0,
          const float* __restrict__ b1, const float* __restrict__ b2,
          const float* __restrict__ b3,
          const float* __restrict__ wf, const float* __restrict__ bf,
          float* __restrict__ out) {
    extern __shared__ __align__(16) unsigned char smem[];
    const uint32_t sb = smem_u32(smem);
    float* w0s  = reinterpret_cast<float*>(smem + OFF_W0);
    float* wfs  = reinterpret_cast<float*>(smem + OFF_WF);
    float* b0s  = reinterpret_cast<float*>(smem + OFF_B0);
    float* b123 = reinterpret_cast<float*>(smem + OFF_B123);
    float* xs   = reinterpret_cast<float*>(smem + OFF_X);
    float* pbuf = reinterpret_cast<float*>(smem + OFF_PBUF);

    const int tid  = threadIdx.x;
    const int lane = tid & 31;
    const int wid  = tid >> 5;
    const int wm   = wid & 1;          // m-tile: rows wm*32..+31
    const int wn   = wid >> 1;         // n-half: cols wn*128..+127
    const int rl   = lane >> 2;        // 0..7
    const int q    = lane & 3;         // 0..3
    const int m    = blockIdx.x >> 7;
    const int bt   = blockIdx.x & 127;
    const int row0 = bt * 64;
    const int barA = 1 + wm;           // A-hazard pair barrier
    const int barB = 3 + wn;           // B-buffer pair barrier
    const int ptid = tid & 63;         // index within wn pair (contiguous tids)

    // ldmatrix lane addressing
    const int lrow  = lane & 15;
    const int lhalf = lane >> 4;

    const unsigned char* wpm = g_wp + (size_t)m * 48 * 16384;

    // ---- prefetch slab 0 (own wn half: hi 4K + lo 4K) ----
    {
        uint32_t dstb = sb + OFF_WBUF + (uint32_t)(wn * 4096 + ptid * 16);
        const unsigned char* src = wpm + wn * 4096 + ptid * 16;
#pragma unroll
        for (int i = 0; i < 4; i++) {
            cp16(dstb + i * 1024, src + i * 1024);
            cp16(dstb + 8192 + i * 1024, src + 8192 + i * 1024);
        }
        cp_commit();
    }

    // ---- stage small tensors ----
    for (int i = tid; i < 768; i += 128) w0s[i] = w0[m * 768 + i];
    for (int i = tid; i < 768; i += 128) wfs[i] = wf[m * 768 + i];
    for (int i = tid; i < 256; i += 128) {
        b0s[i]        = b0[m * 256 + i];
        b123[i]       = b1[m * 256 + i];
        b123[256 + i] = b2[m * 256 + i];
        b123[512 + i] = b3[m * 256 + i];
    }
    for (int i = tid; i < 192; i += 128) xs[i] = x[(size_t)row0 * 3 + i];
    __syncthreads();   // only full barrier in the kernel

    // ---- layer 0: per-warp region rows [wm*32,+32) x cols [wn*128,+128) ----
    {
        const int rbase = wm * 32, cbase = wn * 128;
#pragma unroll 4
        for (int i = 0; i < 64; i++) {
            int pid = lane + i * 32;
            int r = rbase + (pid >> 6);
            int c = cbase + (pid & 63) * 2;
            float x0 = xs[r * 3], x1 = xs[r * 3 + 1], x2 = xs[r * 3 + 2];
            float p0 = fmaf(x2, w0s[c * 3 + 2], fmaf(x1, w0s[c * 3 + 1],
                       fmaf(x0, w0s[c * 3 + 0], b0s[c])));
            float p1 = fmaf(x2, w0s[c * 3 + 5], fmaf(x1, w0s[c * 3 + 4],
                       fmaf(x0, w0s[c * 3 + 3], b0s[c + 1])));
            float v0 = __sinf(W0F * p0);
            float v1 = __sinf(W0F * p1);
            uint32_t ao = aoff(r, c);
            *reinterpret_cast<uint32_t*>(smem + OFF_AHI + ao) = pack2(v0, v1);
            *reinterpret_cast<uint32_t*>(smem + OFF_ALO + ao) = pack2lo(v0, v1);
        }
    }
    barn(barA);   // wm-pair's A writes visible before its layer-1 MMA reads

    // ---- 3 hidden layers over 48 k16 weight slabs ----
    int t = 0;
#pragma unroll 1
    for (int L = 0; L < 3; L++) {
        float acc[16][2][4];
#pragma unroll
        for (int n = 0; n < 16; n++)
#pragma unroll
            for (int f = 0; f < 2; f++)
#pragma unroll
                for (int v = 0; v < 4; v++) acc[n][f][v] = 0.0f;

        uint32_t ah[2][4], al[2][4];

#pragma unroll 1
        for (int s = 0; s < 16; s++, t++) {
            cp_wait0();
            barn(barB);   // wn pair: slab t staged; pair done reading buf (t-1)&1
            if (t < 47) {
                uint32_t dstb = sb + OFF_WBUF + ((t + 1) & 1) * 16384
                              + (uint32_t)(wn * 4096 + ptid * 16);
                const unsigned char* src = wpm + (size_t)(t + 1) * 16384
                                         + wn * 4096 + ptid * 16;
#pragma unroll
                for (int i = 0; i < 4; i++) {
                    cp16(dstb + i * 1024, src + i * 1024);
                    cp16(dstb + 8192 + i * 1024, src + 8192 + i * 1024);
                }
                cp_commit();
            }
            const unsigned char* wb = smem + OFF_WBUF + (t & 1) * 16384;

            // A fragments for this k16 slab via ldmatrix.x4 (hi & lo, f=0,1)
            {
                int c3 = s * 2 + lhalf;
#pragma unroll
                for (int f = 0; f < 2; f++) {
                    int row = wm * 32 + f * 16 + lrow;
                    uint32_t ad = sb + (uint32_t)(row * 512 + ((c3 ^ (row & 7)) << 4));
                    ldsm4(ah[f], ad);
                    ldsm4(al[f], ad + 32768);
                }
            }
#pragma unroll
            for (int n = 0; n < 16; n++) {
                int o = wn * 128 + n * 8 + rl;
                uint2 bh = *reinterpret_cast<const uint2*>(wb + o * 32 + q * 8);
                uint2 bl = *reinterpret_cast<const uint2*>(wb + 8192 + o * 32 + q * 8);
#pragma unroll
                for (int f = 0; f < 2; f++) {
                    mma16816(acc[n][f], ah[f], bh.x, bh.y);
                    mma16816(acc[n][f], al[f], bh.x, bh.y);
                    mma16816(acc[n][f], ah[f], bl.x, bl.y);
                }
            }
        }

        barn(barA);   // wm pair done READING its A rows before overwrite

        if (L < 2) {
            const float* bl = b123 + L * 256;
#pragma unroll
            for (int n = 0; n < 16; n++) {
#pragma unroll
                for (int f = 0; f < 2; f++) {
                    int r   = wm * 32 + f * 16 + rl;
                    int col = wn * 128 + n * 8 + q * 2;
                    float bb0 = bl[col], bb1 = bl[col + 1];
                    float v0 = __sinf(W0F * (acc[n][f][0] + bb0));
                    float v1 = __sinf(W0F * (acc[n][f][1] + bb1));
                    float v2 = __sinf(W0F * (acc[n][f][2] + bb0));
                    float v3 = __sinf(W0F * (acc[n][f][3] + bb1));
                    uint32_t a0 = aoff(r, col);
                    uint32_t a1 = aoff(r + 8, col);
                    *reinterpret_cast<uint32_t*>(smem + OFF_AHI + a0) = pack2(v0, v1);
                    *reinterpret_cast<uint32_t*>(smem + OFF_ALO + a0) = pack2lo(v0, v1);
                    *reinterpret_cast<uint32_t*>(smem + OFF_AHI + a1) = pack2(v2, v3);
                    *reinterpret_cast<uint32_t*>(smem + OFF_ALO + a1) = pack2lo(v2, v3);
                }
            }
            barn(barA);   // pair writes visible before next-layer MMA reads
        } else {
            // final: sine + wf dot (3 outputs), partial per n-half
            const float* bl = b123 + 512;
            float p[4][3];
#pragma unroll
            for (int i = 0; i < 4; i++)
#pragma unroll
                for (int o = 0; o < 3; o++) p[i][o] = 0.0f;
#pragma unroll
            for (int n = 0; n < 16; n++) {
#pragma unroll
                for (int f = 0; f < 2; f++) {
                    int col = wn * 128 + n * 8 + q * 2;
                    float bb0 = bl[col], bb1 = bl[col + 1];
                    float v0 = __sinf(W0F * (acc[n][f][0] + bb0));
                    float v1 = __sinf(W0F * (acc[n][f][1] + bb1));
                    float v2 = __sinf(W0F * (acc[n][f][2] + bb0));
                    float v3 = __sinf(W0F * (acc[n][f][3] + bb1));
#pragma unroll
                    for (int o = 0; o < 3; o++) {
                        float wf0 = wfs[o * 256 + col], wf1 = wfs[o * 256 + col + 1];
                        p[f * 2 + 0][o] = fmaf(v0, wf0, fmaf(v1, wf1, p[f * 2 + 0][o]));
                        p[f * 2 + 1][o] = fmaf(v2, wf0, fmaf(v3, wf1, p[f * 2 + 1][o]));
                    }
                }
            }
#pragma unroll
            for (int i = 0; i < 4; i++)
#pragma unroll
                for (int o = 0; o < 3; o++) {
                    p[i][o] += __shfl_xor_sync(0xffffffffu, p[i][o], 1);
                    p[i][o] += __shfl_xor_sync(0xffffffffu, p[i][o], 2);
                }
            // pbuf[wm][wn][32 rows x 3]
            if (q == 0) {
#pragma unroll
                for (int f = 0; f < 2; f++)
#pragma unroll
                    for (int pr = 0; pr < 2; pr++) {
                        int rloc = f * 16 + pr * 8 + rl;   // 0..31 in wm tile
#pragma unroll
                        for (int o = 0; o < 3; o++)
                            pbuf[wm * 192 + wn * 96 + rloc * 3 + o] = p[f * 2 + pr][o];
                    }
            }
            barn(barA);   // both wn halves of this wm tile written
            int etid = wn * 32 + lane;   // 0..63 within wm pair
            for (int i = etid; i < 96; i += 64) {
                int rloc = i / 3, o = i - rloc * 3;
                float v = pbuf[wm * 192 + i] + pbuf[wm * 192 + 96 + i] + bf[m * 3 + o];
                out[((size_t)(row0 + wm * 32 + rloc) * Mexp + m) * 3 + o] = v;
            }
        }
    }
}

// ---------------------------------------------------------------------------
extern "C" void kernel_launch(void* const* d_in, const int* in_sizes, int n_in,
                              void* d_out, int out_size) {
    (void)in_sizes; (void)n_in; (void)out_size;
    const float* x  = (const float*)d_in[0];
    const float* w0 = (const float*)d_in[1];
    const float* b0 = (const float*)d_in[2];
    const float* w1 = (const float*)d_in[3];
    const float* b1 = (const float*)d_in[4];
    const float* w2 = (const float*)d_in[5];
    const float* b2 = (const float*)d_in[6];
    const float* w3 = (const float*)d_in[7];
    const float* b3 = (const float*)d_in[8];
    const float* wf = (const float*)d_in[9];
    const float* bf = (const float*)d_in[10];
    float* out = (float*)d_out;

    cudaFuncSetAttribute(siren_mma, cudaFuncAttributeMaxDynamicSharedMemorySize,
                         SMEM_TOTAL);

    prep_weights<<<1024, 256>>>(w1, 0);
    prep_weights<<<1024, 256>>>(w2, 1);
    prep_weights<<<1024, 256>>>(w3, 2);

    siren_mma<<<Mexp * (Bdim / 64), 128, SMEM_TOTAL>>>(
        x, w0, b0, b1, b2, b3, wf, bf, out);
}

// round 7
// speedup vs baseline: 1.2195x; 1.0184x over previous
#include <cuda_runtime.h>
#include <cuda_bf16.h>
#include <cstdint>

// ===========================================================================
// PackedSirenExperts via mma.sync m16n8k16 bf16 (portable PTX, compute_103).
// R7 = R6 + RAW-chain break in the MMA mainloop: each k16 slab issues three
// passes over the 16 n-tiles (ah*bh, al*bh, ah*bl) so each accumulator quad
// is rewritten only every ~32 MMAs (was every 1-2 -> scoreboard stalls).
// Named pair-barriers for A-tile (wm pair) and B-buffer (wn pair) hazards.
// 3-term bf16 split (fp32 accum): D += Ahi*Whi + Alo*Whi + Ahi*Wlo.
// CTA = (expert, 64 rows), 128 thr = 2(wm) x 2(wn), warp tile 32x128.
// 2 CTAs/SM (110.8 KB smem).
// ===========================================================================

namespace {
constexpr int Mexp = 64;
constexpr int Bdim = 8192;
constexpr float W0F = 30.0f;

constexpr int OFF_AHI  = 0;          // 64 rows x 512B swizzled bf16 (32K)
constexpr int OFF_ALO  = 32768;      // 32K
constexpr int OFF_WBUF = 65536;      // 2 x 16384 (double-buffered k16 slab)
constexpr int OFF_W0   = 98304;      // 768 f
constexpr int OFF_WF   = 101376;     // 768 f
constexpr int OFF_B0   = 104448;     // 256 f
constexpr int OFF_B123 = 105472;     // 768 f
constexpr int OFF_X    = 108544;     // 192 f
constexpr int OFF_PBUF = 109312;     // 384 f
constexpr int SMEM_TOTAL = 110848;
}

// prepped weights: slab blob = [m][layer*16 + s] of 16KB:
//   [hi: 256 o-rows x 32B][lo: 256 x 32B]; row = 4 q-words (uint2):
//   {bf16x2(k=2q,2q+1), bf16x2(k=2q+8,2q+9)} within the 16-wide k slab.
__device__ __align__(16) unsigned char g_wp[(size_t)Mexp * 48 * 16384];

// ---------------------------------------------------------------------------
__device__ __forceinline__ uint32_t smem_u32(const void* p) {
    uint32_t a;
    asm("{ .reg .u64 t; cvta.to.shared.u64 t, %1; cvt.u32.u64 %0, t; }" : "=r"(a) : "l"(p));
    return a;
}
__device__ __forceinline__ void cp16(uint32_t s, const void* g) {
    asm volatile("cp.async.cg.shared.global [%0], [%1], 16;" :: "r"(s), "l"(g));
}
__device__ __forceinline__ void cp_commit() { asm volatile("cp.async.commit_group;"); }
__device__ __forceinline__ void cp_wait0() {
    asm volatile("cp.async.wait_group 0;" ::: "memory");
}
__device__ __forceinline__ uint32_t pack2(float v0, float v1) {
    __nv_bfloat162 t = __floats2bfloat162_rn(v0, v1);
    return *reinterpret_cast<uint32_t*>(&t);
}
__device__ __forceinline__ uint32_t pack2lo(float v0, float v1) {
    __nv_bfloat16 h0 = __float2bfloat16(v0);
    __nv_bfloat16 h1 = __float2bfloat16(v1);
    __nv_bfloat162 t = __floats2bfloat162_rn(v0 - __bfloat162float(h0),
                                             v1 - __bfloat162float(h1));
    return *reinterpret_cast<uint32_t*>(&t);
}
// A swizzled byte offset: row r (0..63), col k (0..255) bf16
__device__ __forceinline__ uint32_t aoff(int r, int k) {
    return (uint32_t)(r * 512 + ((((k >> 3) ^ (r & 7)) << 4) | ((k & 7) * 2)));
}
__device__ __forceinline__ void mma16816(float* d, const uint32_t* a,
                                         uint32_t b0, uint32_t b1) {
    asm volatile(
        "mma.sync.aligned.m16n8k16.row.col.f32.bf16.bf16.f32 "
        "{%0,%1,%2,%3}, {%4,%5,%6,%7}, {%8,%9}, {%0,%1,%2,%3};"
        : "+f"(d[0]), "+f"(d[1]), "+f"(d[2]), "+f"(d[3])
        : "r"(a[0]), "r"(a[1]), "r"(a[2]), "r"(a[3]), "r"(b0), "r"(b1));
}
__device__ __forceinline__ void ldsm4(uint32_t* r, uint32_t addr) {
    asm volatile("ldmatrix.sync.aligned.m8n8.x4.shared.b16 {%0,%1,%2,%3}, [%4];"
                 : "=r"(r[0]), "=r"(r[1]), "=r"(r[2]), "=r"(r[3]) : "r"(addr));
}
__device__ __forceinline__ void barn(int id) {
    asm volatile("bar.sync %0, 64;" :: "r"(id) : "memory");
}

// ---------------------------------------------------------------------------
// Prep: fp32 W[m][o][i] -> k16-slab blobs (hi 8K | lo 8K per 16KB slab).
// ---------------------------------------------------------------------------
__global__ void prep_weights(const float* __restrict__ w, int layer) {
    int id = blockIdx.x * blockDim.x + threadIdx.x;   // 262144
    int o = id & 255;
    int s = (id >> 8) & 15;
    int m = id >> 12;
    const float* src = w + ((size_t)m * 256 + o) * 256 + s * 16;
    unsigned char* dst = g_wp + (size_t)(m * 48 + layer * 16 + s) * 16384 + o * 32;
#pragma unroll
    for (int q = 0; q < 4; q++) {
        float f0 = src[2 * q],     f1 = src[2 * q + 1];
        float f2 = src[2 * q + 8], f3 = src[2 * q + 9];
        uint2 hv, lv;
        hv.x = pack2(f0, f1);   hv.y = pack2(f2, f3);
        lv.x = pack2lo(f0, f1); lv.y = pack2lo(f2, f3);
        *reinterpret_cast<uint2*>(dst + q * 8) = hv;
        *reinterpret_cast<uint2*>(dst + 8192 + q * 8) = lv;
    }
}

// ---------------------------------------------------------------------------
// Main kernel. grid = Mexp*128 = 8192 CTAs (expert-major), 128 threads.
// ---------------------------------------------------------------------------
__global__ void __launch_bounds__(128, 2)
siren_mma(const float* __restrict__ x,
          const float* __restrict__ w0, const float* __restrict__ b0,
          const float* __restrict__ b1, const float* __restrict__ b2,
          const float* __restrict__ b3,
          const float* __restrict__ wf, const float* __restrict__ bf,
          float* __restrict__ out) {
    extern __shared__ __align__(16) unsigned char smem[];
    const uint32_t sb = smem_u32(smem);
    float* w0s  = reinterpret_cast<float*>(smem + OFF_W0);
    float* wfs  = reinterpret_cast<float*>(smem + OFF_WF);
    float* b0s  = reinterpret_cast<float*>(smem + OFF_B0);
    float* b123 = reinterpret_cast<float*>(smem + OFF_B123);
    float* xs   = reinterpret_cast<float*>(smem + OFF_X);
    float* pbuf = reinterpret_cast<float*>(smem + OFF_PBUF);

    const int tid  = threadIdx.x;
    const int lane = tid & 31;
    const int wid  = tid >> 5;
    const int wm   = wid & 1;          // m-tile: rows wm*32..+31
    const int wn   = wid >> 1;         // n-half: cols wn*128..+127
    const int rl   = lane >> 2;        // 0..7
    const int q    = lane & 3;         // 0..3
    const int m    = blockIdx.x >> 7;
    const int bt   = blockIdx.x & 127;
    const int row0 = bt * 64;
    const int barA = 1 + wm;           // A-hazard pair barrier
    const int barB = 3 + wn;           // B-buffer pair barrier
    const int ptid = tid & 63;         // index within wn pair

    // ldmatrix lane addressing
    const int lrow  = lane & 15;
    const int lhalf = lane >> 4;

    const unsigned char* wpm = g_wp + (size_t)m * 48 * 16384;

    // ---- prefetch slab 0 (own wn half: hi 4K + lo 4K) ----
    {
        uint32_t dstb = sb + OFF_WBUF + (uint32_t)(wn * 4096 + ptid * 16);
        const unsigned char* src = wpm + wn * 4096 + ptid * 16;
#pragma unroll
        for (int i = 0; i < 4; i++) {
            cp16(dstb + i * 1024, src + i * 1024);
            cp16(dstb + 8192 + i * 1024, src + 8192 + i * 1024);
        }
        cp_commit();
    }

    // ---- stage small tensors ----
    for (int i = tid; i < 768; i += 128) w0s[i] = w0[m * 768 + i];
    for (int i = tid; i < 768; i += 128) wfs[i] = wf[m * 768 + i];
    for (int i = tid; i < 256; i += 128) {
        b0s[i]        = b0[m * 256 + i];
        b123[i]       = b1[m * 256 + i];
        b123[256 + i] = b2[m * 256 + i];
        b123[512 + i] = b3[m * 256 + i];
    }
    for (int i = tid; i < 192; i += 128) xs[i] = x[(size_t)row0 * 3 + i];
    __syncthreads();   // only full barrier in the kernel

    // ---- layer 0 ----
    {
        const int rbase = wm * 32, cbase = wn * 128;
#pragma unroll 4
        for (int i = 0; i < 64; i++) {
            int pid = lane + i * 32;
            int r = rbase + (pid >> 6);
            int c = cbase + (pid & 63) * 2;
            float x0 = xs[r * 3], x1 = xs[r * 3 + 1], x2 = xs[r * 3 + 2];
            float p0 = fmaf(x2, w0s[c * 3 + 2], fmaf(x1, w0s[c * 3 + 1],
                       fmaf(x0, w0s[c * 3 + 0], b0s[c])));
            float p1 = fmaf(x2, w0s[c * 3 + 5], fmaf(x1, w0s[c * 3 + 4],
                       fmaf(x0, w0s[c * 3 + 3], b0s[c + 1])));
            float v0 = __sinf(W0F * p0);
            float v1 = __sinf(W0F * p1);
            uint32_t ao = aoff(r, c);
            *reinterpret_cast<uint32_t*>(smem + OFF_AHI + ao) = pack2(v0, v1);
            *reinterpret_cast<uint32_t*>(smem + OFF_ALO + ao) = pack2lo(v0, v1);
        }
    }
    barn(barA);

    // ---- 3 hidden layers over 48 k16 weight slabs ----
    int t = 0;
#pragma unroll 1
    for (int L = 0; L < 3; L++) {
        float acc[16][2][4];
#pragma unroll
        for (int n = 0; n < 16; n++)
#pragma unroll
            for (int f = 0; f < 2; f++)
#pragma unroll
                for (int v = 0; v < 4; v++) acc[n][f][v] = 0.0f;

        uint32_t ah[2][4], al[2][4];

#pragma unroll 1
        for (int s = 0; s < 16; s++, t++) {
            cp_wait0();
            barn(barB);
            if (t < 47) {
                uint32_t dstb = sb + OFF_WBUF + ((t + 1) & 1) * 16384
                              + (uint32_t)(wn * 4096 + ptid * 16);
                const unsigned char* src = wpm + (size_t)(t + 1) * 16384
                                         + wn * 4096 + ptid * 16;
#pragma unroll
                for (int i = 0; i < 4; i++) {
                    cp16(dstb + i * 1024, src + i * 1024);
                    cp16(dstb + 8192 + i * 1024, src + 8192 + i * 1024);
                }
                cp_commit();
            }
            const unsigned char* wb = smem + OFF_WBUF + (t & 1) * 16384;

            // A fragments for this k16 slab (ldmatrix.x4, hi & lo, f=0,1)
            {
                int c3 = s * 2 + lhalf;
#pragma unroll
                for (int f = 0; f < 2; f++) {
                    int row = wm * 32 + f * 16 + lrow;
                    uint32_t ad = sb + (uint32_t)(row * 512 + ((c3 ^ (row & 7)) << 4));
                    ldsm4(ah[f], ad);
                    ldsm4(al[f], ad + 32768);
                }
            }

            // ---- pass 1: Ahi * Whi ----
#pragma unroll
            for (int n = 0; n < 16; n++) {
                int o = wn * 128 + n * 8 + rl;
                uint2 bh = *reinterpret_cast<const uint2*>(wb + o * 32 + q * 8);
                mma16816(acc[n][0], ah[0], bh.x, bh.y);
                mma16816(acc[n][1], ah[1], bh.x, bh.y);
            }
            // ---- pass 2: Alo * Whi ----
#pragma unroll
            for (int n = 0; n < 16; n++) {
                int o = wn * 128 + n * 8 + rl;
                uint2 bh = *reinterpret_cast<const uint2*>(wb + o * 32 + q * 8);
                mma16816(acc[n][0], al[0], bh.x, bh.y);
                mma16816(acc[n][1], al[1], bh.x, bh.y);
            }
            // ---- pass 3: Ahi * Wlo ----
#pragma unroll
            for (int n = 0; n < 16; n++) {
                int o = wn * 128 + n * 8 + rl;
                uint2 bl = *reinterpret_cast<const uint2*>(wb + 8192 + o * 32 + q * 8);
                mma16816(acc[n][0], ah[0], bl.x, bl.y);
                mma16816(acc[n][1], ah[1], bl.x, bl.y);
            }
        }

        barn(barA);   // wm pair done READING its A rows before overwrite

        if (L < 2) {
            const float* bl = b123 + L * 256;
#pragma unroll
            for (int n = 0; n < 16; n++) {
#pragma unroll
                for (int f = 0; f < 2; f++) {
                    int r   = wm * 32 + f * 16 + rl;
                    int col = wn * 128 + n * 8 + q * 2;
                    float bb0 = bl[col], bb1 = bl[col + 1];
                    float v0 = __sinf(W0F * (acc[n][f][0] + bb0));
                    float v1 = __sinf(W0F * (acc[n][f][1] + bb1));
                    float v2 = __sinf(W0F * (acc[n][f][2] + bb0));
                    float v3 = __sinf(W0F * (acc[n][f][3] + bb1));
                    uint32_t a0 = aoff(r, col);
                    uint32_t a1 = aoff(r + 8, col);
                    *reinterpret_cast<uint32_t*>(smem + OFF_AHI + a0) = pack2(v0, v1);
                    *reinterpret_cast<uint32_t*>(smem + OFF_ALO + a0) = pack2lo(v0, v1);
                    *reinterpret_cast<uint32_t*>(smem + OFF_AHI + a1) = pack2(v2, v3);
                    *reinterpret_cast<uint32_t*>(smem + OFF_ALO + a1) = pack2lo(v2, v3);
                }
            }
            barn(barA);   // pair writes visible before next-layer MMA reads
        } else {
            // final: sine + wf dot (3 outputs), partial per n-half
            const float* bl = b123 + 512;
            float p[4][3];
#pragma unroll
            for (int i = 0; i < 4; i++)
#pragma unroll
                for (int o = 0; o < 3; o++) p[i][o] = 0.0f;
#pragma unroll
            for (int n = 0; n < 16; n++) {
#pragma unroll
                for (int f = 0; f < 2; f++) {
                    int col = wn * 128 + n * 8 + q * 2;
                    float bb0 = bl[col], bb1 = bl[col + 1];
                    float v0 = __sinf(W0F * (acc[n][f][0] + bb0));
                    float v1 = __sinf(W0F * (acc[n][f][1] + bb1));
                    float v2 = __sinf(W0F * (acc[n][f][2] + bb0));
                    float v3 = __sinf(W0F * (acc[n][f][3] + bb1));
#pragma unroll
                    for (int o = 0; o < 3; o++) {
                        float wf0 = wfs[o * 256 + col], wf1 = wfs[o * 256 + col + 1];
                        p[f * 2 + 0][o] = fmaf(v0, wf0, fmaf(v1, wf1, p[f * 2 + 0][o]));
                        p[f * 2 + 1][o] = fmaf(v2, wf0, fmaf(v3, wf1, p[f * 2 + 1][o]));
                    }
                }
            }
#pragma unroll
            for (int i = 0; i < 4; i++)
#pragma unroll
                for (int o = 0; o < 3; o++) {
                    p[i][o] += __shfl_xor_sync(0xffffffffu, p[i][o], 1);
                    p[i][o] += __shfl_xor_sync(0xffffffffu, p[i][o], 2);
                }
            if (q == 0) {
#pragma unroll
                for (int f = 0; f < 2; f++)
#pragma unroll
                    for (int pr = 0; pr < 2; pr++) {
                        int rloc = f * 16 + pr * 8 + rl;   // 0..31 in wm tile
#pragma unroll
                        for (int o = 0; o < 3; o++)
                            pbuf[wm * 192 + wn * 96 + rloc * 3 + o] = p[f * 2 + pr][o];
                    }
            }
            barn(barA);
            int etid = wn * 32 + lane;   // 0..63 within wm pair
            for (int i = etid; i < 96; i += 64) {
                int rloc = i / 3, o = i - rloc * 3;
                float v = pbuf[wm * 192 + i] + pbuf[wm * 192 + 96 + i] + bf[m * 3 + o];
                out[((size_t)(row0 + wm * 32 + rloc) * Mexp + m) * 3 + o] = v;
            }
        }
    }
}

// ---------------------------------------------------------------------------
extern "C" void kernel_launch(void* const* d_in, const int* in_sizes, int n_in,
                              void* d_out, int out_size) {
    (void)in_sizes; (void)n_in; (void)out_size;
    const float* x  = (const float*)d_in[0];
    const float* w0 = (const float*)d_in[1];
    const float* b0 = (const float*)d_in[2];
    const float* w1 = (const float*)d_in[3];
    const float* b1 = (const float*)d_in[4];
    const float* w2 = (const float*)d_in[5];
    const float* b2 = (const float*)d_in[6];
    const float* w3 = (const float*)d_in[7];
    const float* b3 = (const float*)d_in[8];
    const float* wf = (const float*)d_in[9];
    const float* bf = (const float*)d_in[10];
    float* out = (float*)d_out;

    cudaFuncSetAttribute(siren_mma, cudaFuncAttributeMaxDynamicSharedMemorySize,
                         SMEM_TOTAL);

    prep_weights<<<1024, 256>>>(w1, 0);
    prep_weights<<<1024, 256>>>(w2, 1);
    prep_weights<<<1024, 256>>>(w3, 2);

    siren_mma<<<Mexp * (Bdim / 64), 128, SMEM_TOTAL>>>(
        x, w0, b0, b1, b2, b3, wf, bf, out);
}